// round 5
// baseline (speedup 1.0000x reference)
#include <cuda_runtime.h>
#include <math.h>

// Shapes (fixed): B=8, L=1024, D=512, H=8, dh=64
//
// Decomposition:
//   K1: Q,K,V = x @ {Wq,Wk,Wv}            (8192x512x512 fp32 SGEMM x3)
//   K2: R2[b,h,l,d] = Q[b,:,h,:] @ WeF     (WeF[:,j] = We[:,1023-j]) ; d = |l-s|
//   K3: flash attention, logits = 0.125 * (q_l . k_s) * R2[l,|l-s|]
//
// Derivation of the pad/reflect/reshape trick: s_rel[l,s] = qe[l, L-1-|l-s|].

static __device__ float g_Q[8192 * 512];
static __device__ float g_K[8192 * 512];
static __device__ float g_V[8192 * 512];
static __device__ float g_R2[67108864];   // [B*H][1024][1024] = 256 MB

// ---------------------------------------------------------------------------
// K1: C = x @ W,  M=8192, N=512, K=512.  blockIdx.z selects {Wq,Wk,Wv}.
// 128x128 tile, BK=16, 256 threads, 8x8 micro split as 4+4 rows/cols.
// ---------------------------------------------------------------------------
__global__ __launch_bounds__(256) void k_qkv_gemm(
    const float* __restrict__ x,
    const float* __restrict__ Wq,
    const float* __restrict__ Wk,
    const float* __restrict__ Wv)
{
    __shared__ float As[16][132];   // [k][m], padded (stride 132) for store conflicts
    __shared__ float Bs[16][128];   // [k][n]

    const float* __restrict__ W = (blockIdx.z == 0) ? Wq : (blockIdx.z == 1) ? Wk : Wv;
    float* __restrict__ C = (blockIdx.z == 0) ? g_Q : (blockIdx.z == 1) ? g_K : g_V;

    const int m0 = blockIdx.y * 128;
    const int n0 = blockIdx.x * 128;
    const int tid = threadIdx.x;
    const int ty = tid >> 4;
    const int tx = tid & 15;

    float acc[8][8];
#pragma unroll
    for (int i = 0; i < 8; i++)
#pragma unroll
        for (int j = 0; j < 8; j++) acc[i][j] = 0.f;

    for (int k0 = 0; k0 < 512; k0 += 16) {
#pragma unroll
        for (int r = 0; r < 8; r++) {
            int idx = tid + r * 256;
            int m = idx >> 4, k = idx & 15;
            As[k][m] = x[(size_t)(m0 + m) * 512 + (k0 + k)];
        }
#pragma unroll
        for (int r = 0; r < 8; r++) {
            int idx = tid + r * 256;
            int k = idx >> 7, n = idx & 127;
            Bs[k][n] = W[(size_t)(k0 + k) * 512 + (n0 + n)];
        }
        __syncthreads();
#pragma unroll
        for (int k = 0; k < 16; k++) {
            float a[8], b[8];
            *(float4*)&a[0] = *(const float4*)&As[k][ty * 4];
            *(float4*)&a[4] = *(const float4*)&As[k][64 + ty * 4];
            *(float4*)&b[0] = *(const float4*)&Bs[k][tx * 4];
            *(float4*)&b[4] = *(const float4*)&Bs[k][64 + tx * 4];
#pragma unroll
            for (int i = 0; i < 8; i++)
#pragma unroll
                for (int j = 0; j < 8; j++)
                    acc[i][j] = fmaf(a[i], b[j], acc[i][j]);
        }
        __syncthreads();
    }

#pragma unroll
    for (int i = 0; i < 8; i++) {
        int m = m0 + ((i < 4) ? (ty * 4 + i) : (64 + ty * 4 + (i - 4)));
#pragma unroll
        for (int jg = 0; jg < 2; jg++) {
            float4 v = make_float4(acc[i][jg * 4 + 0], acc[i][jg * 4 + 1],
                                   acc[i][jg * 4 + 2], acc[i][jg * 4 + 3]);
            *(float4*)&C[(size_t)m * 512 + n0 + jg * 64 + tx * 4] = v;
        }
    }
}

// ---------------------------------------------------------------------------
// K2: R2[bh] = Q_head[1024,64] @ WeF[64,1024]   (WeF[k][n] = We[k][1023-n])
// Same tiling as K1, K=64. blockIdx.z = bh in [0,64).
// ---------------------------------------------------------------------------
__global__ __launch_bounds__(256) void k_rel_gemm(const float* __restrict__ We)
{
    __shared__ float As[16][132];
    __shared__ float Bs[16][128];

    const int bh = blockIdx.z;
    const float* __restrict__ A = g_Q + (size_t)(bh >> 3) * 1024 * 512 + (size_t)(bh & 7) * 64;
    float* __restrict__ C = g_R2 + (size_t)bh * 1024 * 1024;

    const int m0 = blockIdx.y * 128;
    const int n0 = blockIdx.x * 128;
    const int tid = threadIdx.x;
    const int ty = tid >> 4;
    const int tx = tid & 15;

    float acc[8][8];
#pragma unroll
    for (int i = 0; i < 8; i++)
#pragma unroll
        for (int j = 0; j < 8; j++) acc[i][j] = 0.f;

    for (int k0 = 0; k0 < 64; k0 += 16) {
#pragma unroll
        for (int r = 0; r < 8; r++) {
            int idx = tid + r * 256;
            int m = idx >> 4, k = idx & 15;
            As[k][m] = A[(size_t)(m0 + m) * 512 + (k0 + k)];
        }
#pragma unroll
        for (int r = 0; r < 8; r++) {
            int idx = tid + r * 256;
            int k = idx >> 7, n = idx & 127;
            Bs[k][n] = We[(size_t)(k0 + k) * 1024 + (1023 - (n0 + n))];
        }
        __syncthreads();
#pragma unroll
        for (int k = 0; k < 16; k++) {
            float a[8], b[8];
            *(float4*)&a[0] = *(const float4*)&As[k][ty * 4];
            *(float4*)&a[4] = *(const float4*)&As[k][64 + ty * 4];
            *(float4*)&b[0] = *(const float4*)&Bs[k][tx * 4];
            *(float4*)&b[4] = *(const float4*)&Bs[k][64 + tx * 4];
#pragma unroll
            for (int i = 0; i < 8; i++)
#pragma unroll
                for (int j = 0; j < 8; j++)
                    acc[i][j] = fmaf(a[i], b[j], acc[i][j]);
        }
        __syncthreads();
    }

#pragma unroll
    for (int i = 0; i < 8; i++) {
        int m = m0 + ((i < 4) ? (ty * 4 + i) : (64 + ty * 4 + (i - 4)));
#pragma unroll
        for (int jg = 0; jg < 2; jg++) {
            float4 v = make_float4(acc[i][jg * 4 + 0], acc[i][jg * 4 + 1],
                                   acc[i][jg * 4 + 2], acc[i][jg * 4 + 3]);
            *(float4*)&C[(size_t)m * 1024 + n0 + jg * 64 + tx * 4] = v;
        }
    }
}

// ---------------------------------------------------------------------------
// K3: flash attention. Block = (b, h, 64 query rows). 256 threads, 4x4 micro.
// Dynamic smem: Qt/Kt transposed [d][l|s], Vs natural [s][d], Ps [l][s].
// ---------------------------------------------------------------------------
__global__ __launch_bounds__(256) void k_attn(float* __restrict__ out)
{
    extern __shared__ float sm[];
    float (*Qt)[68] = (float(*)[68])(sm);
    float (*Kt)[68] = (float(*)[68])(sm + 64 * 68);
    float (*Vs)[68] = (float(*)[68])(sm + 2 * 64 * 68);
    float (*Ps)[68] = (float(*)[68])(sm + 3 * 64 * 68);

    const int l0 = blockIdx.x * 64;
    const int h  = blockIdx.y;
    const int b  = blockIdx.z;
    const int tid = threadIdx.x;
    const int ty = tid >> 4;
    const int tx = tid & 15;

    const size_t headoff = (size_t)b * 1024 * 512 + (size_t)h * 64;
    const float* __restrict__ Qg = g_Q + headoff;
    const float* __restrict__ Kg = g_K + headoff;
    const float* __restrict__ Vg = g_V + headoff;
    const float* __restrict__ R  = g_R2 + (size_t)(b * 8 + h) * 1024 * 1024;

    // Load Q tile transposed: Qt[d][l_local]
    {
        int row = tid >> 2;            // l_local 0..63
        int g4  = (tid & 3) * 4;       // d base, i-step 16 (2-way STS conflicts)
        const float* src = Qg + (size_t)(l0 + row) * 512;
#pragma unroll
        for (int i = 0; i < 4; i++) {
            int d = g4 + i * 16;
            float4 v = *(const float4*)(src + d);
            Qt[d + 0][row] = v.x;
            Qt[d + 1][row] = v.y;
            Qt[d + 2][row] = v.z;
            Qt[d + 3][row] = v.w;
        }
    }

    float m_[4], r_[4], O[4][4];
#pragma unroll
    for (int i = 0; i < 4; i++) {
        m_[i] = -INFINITY;
        r_[i] = 0.f;
#pragma unroll
        for (int j = 0; j < 4; j++) O[i][j] = 0.f;
    }

    const float scale = 0.125f;

    for (int s0 = 0; s0 < 1024; s0 += 64) {
        __syncthreads();   // previous PV done (and Qt visible on first iter)
        {
            int row = tid >> 2;
            int g4  = (tid & 3) * 4;
            const float* ks = Kg + (size_t)(s0 + row) * 512;
            const float* vs = Vg + (size_t)(s0 + row) * 512;
#pragma unroll
            for (int i = 0; i < 4; i++) {
                int d = g4 + i * 16;
                float4 kv = *(const float4*)(ks + d);
                Kt[d + 0][row] = kv.x;
                Kt[d + 1][row] = kv.y;
                Kt[d + 2][row] = kv.z;
                Kt[d + 3][row] = kv.w;
                *(float4*)&Vs[row][d] = *(const float4*)(vs + d);
            }
        }
        __syncthreads();

        // S = Q @ K^T  (64x64, k=64), 4x4 fragment per thread
        float S[4][4];
#pragma unroll
        for (int i = 0; i < 4; i++)
#pragma unroll
            for (int j = 0; j < 4; j++) S[i][j] = 0.f;

#pragma unroll 16
        for (int d = 0; d < 64; d++) {
            float4 qa = *(const float4*)&Qt[d][ty * 4];
            float4 kb = *(const float4*)&Kt[d][tx * 4];
            float a_[4] = {qa.x, qa.y, qa.z, qa.w};
            float b_[4] = {kb.x, kb.y, kb.z, kb.w};
#pragma unroll
            for (int i = 0; i < 4; i++)
#pragma unroll
                for (int j = 0; j < 4; j++)
                    S[i][j] = fmaf(a_[i], b_[j], S[i][j]);
        }

        // logits = scale * S * R2[l, |l-s|]; online softmax; store P
#pragma unroll
        for (int i = 0; i < 4; i++) {
            const int l = l0 + ty * 4 + i;
            const float* Rrow = R + (size_t)l * 1024;
#pragma unroll
            for (int j = 0; j < 4; j++) {
                int s = s0 + tx * 4 + j;
                int dd = l - s;
                dd = (dd < 0) ? -dd : dd;
                S[i][j] = scale * S[i][j] * Rrow[dd];
            }
            float rm = fmaxf(fmaxf(S[i][0], S[i][1]), fmaxf(S[i][2], S[i][3]));
#pragma unroll
            for (int w = 1; w < 16; w <<= 1)
                rm = fmaxf(rm, __shfl_xor_sync(0xffffffffu, rm, w));
            float mn = fmaxf(m_[i], rm);
            float alpha = __expf(m_[i] - mn);   // exp(-inf)=0 on first tile
            float ssum = 0.f;
#pragma unroll
            for (int j = 0; j < 4; j++) {
                S[i][j] = __expf(S[i][j] - mn);
                ssum += S[i][j];
            }
#pragma unroll
            for (int w = 1; w < 16; w <<= 1)
                ssum += __shfl_xor_sync(0xffffffffu, ssum, w);
            r_[i] = r_[i] * alpha + ssum;
            m_[i] = mn;
#pragma unroll
            for (int j = 0; j < 4; j++) O[i][j] *= alpha;
            *(float4*)&Ps[ty * 4 + i][tx * 4] =
                make_float4(S[i][0], S[i][1], S[i][2], S[i][3]);
        }
        __syncthreads();

        // O += P @ V  (64x64 @ 64x64)
#pragma unroll 16
        for (int s = 0; s < 64; s++) {
            float4 vb = *(const float4*)&Vs[s][tx * 4];
            float v4[4] = {vb.x, vb.y, vb.z, vb.w};
            float p[4] = {Ps[ty * 4 + 0][s], Ps[ty * 4 + 1][s],
                          Ps[ty * 4 + 2][s], Ps[ty * 4 + 3][s]};
#pragma unroll
            for (int i = 0; i < 4; i++)
#pragma unroll
                for (int j = 0; j < 4; j++)
                    O[i][j] = fmaf(p[i], v4[j], O[i][j]);
        }
    }

    // Epilogue: out[b, l, h*64 + d] = O / r
#pragma unroll
    for (int i = 0; i < 4; i++) {
        float inv = 1.f / r_[i];
        float4 o = make_float4(O[i][0] * inv, O[i][1] * inv,
                               O[i][2] * inv, O[i][3] * inv);
        *(float4*)&out[(size_t)(b * 1024 + l0 + ty * 4 + i) * 512 + h * 64 + tx * 4] = o;
    }
}

// ---------------------------------------------------------------------------

extern "C" void kernel_launch(void* const* d_in, const int* in_sizes, int n_in,
                              void* d_out, int out_size)
{
    (void)in_sizes; (void)n_in; (void)out_size;
    const float* x  = (const float*)d_in[0];
    const float* Wq = (const float*)d_in[1];
    const float* Wk = (const float*)d_in[2];
    const float* Wv = (const float*)d_in[3];
    const float* We = (const float*)d_in[4];
    float* out = (float*)d_out;

    const int SMEM3 = 4 * 64 * 68 * (int)sizeof(float);   // 69632 B
    cudaFuncSetAttribute(k_attn, cudaFuncAttributeMaxDynamicSharedMemorySize, SMEM3);

    k_qkv_gemm<<<dim3(4, 64, 3), 256>>>(x, Wq, Wk, Wv);
    k_rel_gemm<<<dim3(8, 8, 64), 256>>>(We);
    k_attn<<<dim3(16, 8, 8), 256, SMEM3>>>(out);
}